// round 12
// baseline (speedup 1.0000x reference)
#include <cuda_runtime.h>
#include <cuda_fp16.h>
#include <math.h>

#define NSC 7
#define NB 8
#define ADIM 512
#define MAPSZ (NB * ADIM * ADIM)       // 2,097,152 cells per scale
#define PTS (NSC * MAPSZ)              // 14,680,064 points per coord set
#define TTY 258                        // tile-row stride (even for uint4)
#define TTX 257                        // tile rows
#define MAPH (TTX * TTY)               // 66306 tiles (8B each) per (map, replica)

// Scratch: 4 shift-replicas per scale; each 2x2 logical tile = 4 x f16 = uint2.
// ~119 MB. INVARIANT: all-zero at entry to every kernel_launch call
// (__device__ globals zero-init at load; k_stats/k_sweep re-zero after use).
__device__ __align__(16) uint2 g_rep[NSC][4][NB * MAPH];
__device__ float        g_sumlog[NSC];
__device__ unsigned int g_max[NSC];     // float bits (values >= 0)
__device__ unsigned int g_nzero[NSC];
__device__ unsigned int g_npos;

// ---------------------------------------------------------------------------
// K1: bilinear scatter, ALL scales — ONE red.global.add.noftz.v2.f16x2 per
// point. Replica (sx,sy) stores logical (x,y) at (x+sx, y+sy); sx=ixf&1,
// sy=iyf&1 puts the 2x2 footprint in exactly one aligned tile.
// Tile halves [0..3] = (dx,dy) = (0,0),(0,1),(1,0),(1,1).
// (Rate = L1tex wavefront floor ~1 lane/cyc/SM for random addresses; R2 vs
// R6 equal-time falsified width/byte effects. This kernel is at the floor.)
// ---------------------------------------------------------------------------
__device__ __forceinline__ void scat1(int s, int b, float r, float c) {
    float xf = fminf(fmaxf(floorf(r), 0.f), 511.f);
    float yf = fminf(fmaxf(floorf(c), 0.f), 511.f);
    float xw = r - xf;
    float yw = c - yf;
    int ix = (int)xf, iy = (int)yf;
    int sx = ix & 1, sy = iy & 1;
    uint2* a = &g_rep[s][sx * 2 + sy][b * MAPH + ((ix + sx) >> 1) * TTY + ((iy + sy) >> 1)];
    float wx0 = 1.f - xw, wy0 = 1.f - yw;
    __half2 lo = __floats2half2_rn(wx0 * wy0, wx0 * yw);   // (0,0),(0,1)
    __half2 hi = __floats2half2_rn(xw * wy0,  xw * yw);    // (1,0),(1,1)
    unsigned ulo = *reinterpret_cast<unsigned*>(&lo);
    unsigned uhi = *reinterpret_cast<unsigned*>(&hi);
    asm volatile("red.global.add.noftz.v2.f16x2 [%0], {%1, %2};"
                 :: "l"(a), "r"(ulo), "r"(uhi)
                 : "memory");
}

__global__ void __launch_bounds__(256) k_scatter(
        const float4* __restrict__ r3, const float4* __restrict__ c3,
        const float4* __restrict__ r4, const float4* __restrict__ c4) {
    int i = blockIdx.x * blockDim.x + threadIdx.x;   // [0, PTS/4)
    if (i >= PTS / 4) return;
    int s = i >> 19;                                 // scale (MAPSZ/4 = 2^19)
    int b = (i >> 16) & 7;                           // batch within scale

    float4 rA = r3[i], cA = c3[i];
    float4 rB = r4[i], cB = c4[i];
    scat1(s, b, rA.x, cA.x); scat1(s, b, rA.y, cA.y);
    scat1(s, b, rA.z, cA.z); scat1(s, b, rA.w, cA.w);
    scat1(s, b, rB.x, cB.x); scat1(s, b, rB.y, cB.y);
    scat1(s, b, rB.z, cB.z); scat1(s, b, rB.w, cB.w);
}

// ---------------------------------------------------------------------------
// K2: fused combine + max + masked log-stats + INTERIOR restore-to-zero.
// CTA = 8x32 threads; each thread handles TWO home tile-pairs, rows bx and
// bx+8, so the CTA covers 16 tile-rows x 32 tile-pairs. Cross-CTA reads only
// touch rows == 0 (mod 16) and tx==0 columns of neighbor CTAs (never zeroed
// here; k_sweep gets them). Intra-CTA read/zero ordering via __syncthreads.
// BCE algebra: sum_{mask} min(lm - log(dm), 100)
//   = (npos - nzero)*lm - sum_{mask,dm>0} log(dm) + 100*nzero
// ---------------------------------------------------------------------------
__device__ __forceinline__ float lohalf(unsigned u) { return __half2float(__ushort_as_half((unsigned short)(u & 0xFFFF))); }
__device__ __forceinline__ float hihalf(unsigned u) { return __half2float(__ushort_as_half((unsigned short)(u >> 16))); }

__device__ __forceinline__ void stat_cell(float d, float t, float& sl,
                                          unsigned& nz, unsigned& np) {
    if (t == 1.0f) {
        np++;
        if (d == 0.f) nz++;
        else sl += __logf(d);
    }
}

__device__ __forceinline__ void do_home(
        const uint2* __restrict__ r00, const uint2* __restrict__ r01,
        const uint2* __restrict__ r10, const uint2* __restrict__ r11,
        int t00, const float* __restrict__ tp,
        float& mx, float& sl, unsigned& nz, unsigned& np) {
    uint4 A  = *(const uint4*)(r00 + t00);
    uint4 B0 = *(const uint4*)(r01 + t00);
    uint2 B2 = r01[t00 + 2];
    uint4 C0 = *(const uint4*)(r10 + t00);
    uint4 C1 = *(const uint4*)(r10 + t00 + TTY);
    uint4 D0 = *(const uint4*)(r11 + t00);
    uint2 D2 = r11[t00 + 2];
    uint4 D1 = *(const uint4*)(r11 + t00 + TTY);
    uint2 D3 = r11[t00 + TTY + 2];

    // home tile 0: logical block (bx, by)
    float a00 = lohalf(A.x) + hihalf(B0.x) + lohalf(C0.y) + hihalf(D0.y);
    float a01 = hihalf(A.x) + lohalf(B0.z) + hihalf(C0.y) + lohalf(D0.w);
    float a10 = lohalf(A.y) + hihalf(B0.y) + lohalf(C1.x) + hihalf(D1.x);
    float a11 = hihalf(A.y) + lohalf(B0.w) + hihalf(C1.x) + lohalf(D1.z);
    // home tile 1: logical block (bx, by+1)
    float e00 = lohalf(A.z) + hihalf(B0.z) + lohalf(C0.w) + hihalf(D0.w);
    float e01 = hihalf(A.z) + lohalf(B2.x) + hihalf(C0.w) + lohalf(D2.y);
    float e10 = lohalf(A.w) + hihalf(B0.w) + lohalf(C1.z) + hihalf(D1.z);
    float e11 = hihalf(A.w) + lohalf(B2.y) + hihalf(C1.z) + lohalf(D3.x);

    mx = fmaxf(mx, fmaxf(fmaxf(fmaxf(a00, a01), fmaxf(a10, a11)),
                         fmaxf(fmaxf(e00, e01), fmaxf(e10, e11))));

    float4 t0 = *(const float4*)tp;
    float4 t1 = *(const float4*)(tp + ADIM);
    stat_cell(a00, t0.x, sl, nz, np);
    stat_cell(a01, t0.y, sl, nz, np);
    stat_cell(e00, t0.z, sl, nz, np);
    stat_cell(e01, t0.w, sl, nz, np);
    stat_cell(a10, t1.x, sl, nz, np);
    stat_cell(a11, t1.y, sl, nz, np);
    stat_cell(e10, t1.z, sl, nz, np);
    stat_cell(e11, t1.w, sl, nz, np);
}

__global__ void __launch_bounds__(256) k_stats(const float* __restrict__ target) {
    // blockIdx.x in [0, 3584): s(7) | b(8) | bxblk(16) | bypblk(4)
    const int blk    = blockIdx.x;
    const int s      = blk >> 9;
    const int b      = (blk >> 6) & 7;
    const int bxblk  = (blk >> 2) & 15;
    const int bypblk = blk & 3;
    const int tx = threadIdx.x & 31;     // byp within block
    const int ty = threadIdx.x >> 5;     // row within block (home1)
    const int bx0 = bxblk * 16 + ty;     // home1 tile row; home2 = bx0 + 8
    const int byp = bypblk * 32 + tx;
    const int by  = byp * 2;
    const int t0 = b * MAPH + bx0 * TTY + by;   // 16B aligned (TTY, by even)
    const int t1 = t0 + 8 * TTY;

    uint2* __restrict__ w00 = g_rep[s][0];
    uint2* __restrict__ w01 = g_rep[s][1];
    uint2* __restrict__ w10 = g_rep[s][2];
    uint2* __restrict__ w11 = g_rep[s][3];

    float mx = 0.f, sl = 0.f;
    unsigned nz = 0, np = 0;
    {
        const float* tp0 = target + b * (ADIM * ADIM) + (2 * bx0) * ADIM + 2 * by;
        do_home(w00, w01, w10, w11, t0, tp0,             mx, sl, nz, np);
        do_home(w00, w01, w10, w11, t1, tp0 + 16 * ADIM, mx, sl, nz, np);
    }
    #pragma unroll
    for (int o = 16; o; o >>= 1) {
        mx = fmaxf(mx, __shfl_xor_sync(0xFFFFFFFFu, mx, o));
        sl += __shfl_xor_sync(0xFFFFFFFFu, sl, o);
        nz += __shfl_xor_sync(0xFFFFFFFFu, nz, o);
        np += __shfl_xor_sync(0xFFFFFFFFu, np, o);
    }
    __shared__ float    smx[8], ssl[8];
    __shared__ unsigned snz[8], snp[8];
    int w = threadIdx.x >> 5;
    if ((threadIdx.x & 31) == 0) { smx[w] = mx; ssl[w] = sl; snz[w] = nz; snp[w] = np; }
    __syncthreads();   // orders: ALL CTA loads above complete before zeroing

    // Interior restore. home1 (row bx0): cross-CTA-read iff ty==0 (row%16==0)
    // -> skip. home2 (row bx0+8): only read within this CTA -> always zero.
    // tx==0 columns are read by the left CTA -> skip (k_sweep covers).
    if (tx != 0) {
        const uint4 z = make_uint4(0u, 0u, 0u, 0u);
        if (ty != 0) {
            *(uint4*)(w00 + t0) = z;
            *(uint4*)(w01 + t0) = z;
            *(uint4*)(w10 + t0) = z;
            *(uint4*)(w11 + t0) = z;
        }
        *(uint4*)(w00 + t1) = z;
        *(uint4*)(w01 + t1) = z;
        *(uint4*)(w10 + t1) = z;
        *(uint4*)(w11 + t1) = z;
    }

    if (threadIdx.x == 0) {
        float bmx = smx[0], bsl = ssl[0];
        unsigned bnz = snz[0], bnp = snp[0];
        #pragma unroll
        for (int k = 1; k < 8; k++) {
            bmx = fmaxf(bmx, smx[k]); bsl += ssl[k]; bnz += snz[k]; bnp += snp[k];
        }
        atomicMax(&g_max[s], __float_as_uint(bmx));
        atomicAdd(&g_sumlog[s], bsl);
        if (bnz) atomicAdd(&g_nzero[s], bnz);
        if (s == 0) atomicAdd(&g_npos, bnp);
    }
}

// ---------------------------------------------------------------------------
// K3: sweep — zero boundary tiles k_stats skipped: tile rows r % 16 == 0
// (incl. pad row 256: r = rr*16, rr in 0..16) full-width, plus col pairs
// {64k, 64k+1} (k=0..4, incl. pad cols 256/257) all rows, for all 224
// (scale,replica,map) planes. ~12.5 MB. Block 0 also computes the final
// loss (stats already completed in stream order) and resets accumulators.
// ---------------------------------------------------------------------------
#define RM   (NSC * 4 * NB)            // 224 planes
#define ROWI (17 * 129)                // 17 rows x 129 uint4 (full rows)
#define COLI (5 * 257)                 // 5 uint4-cols x 257 rows
#define SWI  (ROWI + COLI)             // 3478 uint4 per plane

__global__ void __launch_bounds__(256) k_sweep(float* __restrict__ out) {
    int gid = blockIdx.x * blockDim.x + threadIdx.x;
    if (gid < RM * SWI) {
        int rm   = gid / SWI;
        int rest = gid - rm * SWI;
        int r, c;
        if (rest < ROWI) {           // full rows 0,16,...,240,256
            int rr = rest / 129;
            r = rr * 16;
            c = (rest - rr * 129) * 2;
        } else {                     // col pairs {0,64,128,192,256}
            int t = rest - ROWI;
            int ci = t / 257;
            c = ci * 64;
            r = t - ci * 257;
        }
        uint2* base = &g_rep[0][0][0] + (size_t)rm * MAPH;
        *(uint4*)(base + r * TTY + c) = make_uint4(0u, 0u, 0u, 0u);
    }
    if (blockIdx.x == 0 && threadIdx.x == 0) {
        float np = (float)g_npos;
        float tot = 0.f;
        #pragma unroll
        for (int i = 0; i < NSC; i++) {
            float lm = logf(__uint_as_float(g_max[i]));
            float nzf = (float)g_nzero[i];
            tot += ((np - nzf) * lm - g_sumlog[i] + 100.f * nzf) / np;
            g_sumlog[i] = 0.f; g_max[i] = 0u; g_nzero[i] = 0u;
        }
        g_npos = 0u;
        out[0] = tot;
    }
}

// ---------------------------------------------------------------------------
// Launch: single stream, 3 nodes: scatter -> stats(+interior restore) -> sweep(+final)
// ---------------------------------------------------------------------------
extern "C" void kernel_launch(void* const* d_in, const int* in_sizes, int n_in,
                              void* d_out, int out_size) {
    const float4* r3 = (const float4*)d_in[0];
    const float4* c3 = (const float4*)d_in[1];
    const float4* r4 = (const float4*)d_in[2];
    const float4* c4 = (const float4*)d_in[3];
    const float*  target = (const float*)d_in[4];
    float* out = (float*)d_out;

    k_scatter<<<PTS / 4 / 256, 256>>>(r3, c3, r4, c4);     // 14336 CTAs
    k_stats<<<NSC * 512, 256>>>(target);                   // 3584 CTAs
    k_sweep<<<(RM * SWI + 255) / 256, 256>>>(out);         // 3043 CTAs
}

// round 13
// speedup vs baseline: 1.0076x; 1.0076x over previous
#include <cuda_runtime.h>
#include <cuda_fp16.h>
#include <math.h>

#define NSC 7
#define NB 8
#define ADIM 512
#define MAPSZ (NB * ADIM * ADIM)       // 2,097,152 cells per scale
#define PTS (NSC * MAPSZ)              // 14,680,064 points per coord set
#define TTY 258                        // tile-row stride (even for uint4)
#define TTX 257                        // tile rows
#define MAPH (TTX * TTY)               // 66306 tiles (8B each) per (map, replica)

// Scratch: 4 shift-replicas per scale; each 2x2 logical tile = 4 x f16 = uint2.
// ~119 MB. INVARIANT: all-zero at entry to every kernel_launch call
// (__device__ globals zero-init at load; k_stats/k_sweep re-zero after use).
__device__ __align__(16) uint2 g_rep[NSC][4][NB * MAPH];
__device__ unsigned int g_mask[MAPSZ / 32];   // 1 bit/cell; fully rewritten each call
__device__ float        g_sumlog[NSC];
__device__ unsigned int g_max[NSC];     // float bits (values >= 0)
__device__ unsigned int g_nzero[NSC];
__device__ unsigned int g_npos;

// ---------------------------------------------------------------------------
// K0: build target bitmask — bit c of word (b*512+r)*16 + c/32 = (target==1).
// 4-bit groups (4-aligned cols) never straddle a word. 8 MB read, 256 KB write.
// ---------------------------------------------------------------------------
__global__ void __launch_bounds__(256) k_mask(const float4* __restrict__ target) {
    int w = blockIdx.x * blockDim.x + threadIdx.x;   // [0, 65536) word index
    const float4* tp = target + w * 8;               // 32 cells
    unsigned m = 0;
    #pragma unroll
    for (int j = 0; j < 8; j++) {
        float4 t = tp[j];
        m |= (t.x == 1.0f ? 1u : 0u) << (4 * j);
        m |= (t.y == 1.0f ? 2u : 0u) << (4 * j);
        m |= (t.z == 1.0f ? 4u : 0u) << (4 * j);
        m |= (t.w == 1.0f ? 8u : 0u) << (4 * j);
    }
    g_mask[w] = m;
}

// ---------------------------------------------------------------------------
// K1: bilinear scatter, ALL scales — ONE red.global.add.noftz.v2.f16x2 per
// point. Replica (sx,sy) stores logical (x,y) at (x+sx, y+sy); sx=ixf&1,
// sy=iyf&1 puts the 2x2 footprint in exactly one aligned tile.
// Tile halves [0..3] = (dx,dy) = (0,0),(0,1),(1,0),(1,1).
// (At the L1tex wavefront floor ~1 lane/cyc/SM for random addresses.)
// ---------------------------------------------------------------------------
__device__ __forceinline__ void scat1(int s, int b, float r, float c) {
    float xf = fminf(fmaxf(floorf(r), 0.f), 511.f);
    float yf = fminf(fmaxf(floorf(c), 0.f), 511.f);
    float xw = r - xf;
    float yw = c - yf;
    int ix = (int)xf, iy = (int)yf;
    int sx = ix & 1, sy = iy & 1;
    uint2* a = &g_rep[s][sx * 2 + sy][b * MAPH + ((ix + sx) >> 1) * TTY + ((iy + sy) >> 1)];
    float wx0 = 1.f - xw, wy0 = 1.f - yw;
    __half2 lo = __floats2half2_rn(wx0 * wy0, wx0 * yw);   // (0,0),(0,1)
    __half2 hi = __floats2half2_rn(xw * wy0,  xw * yw);    // (1,0),(1,1)
    unsigned ulo = *reinterpret_cast<unsigned*>(&lo);
    unsigned uhi = *reinterpret_cast<unsigned*>(&hi);
    asm volatile("red.global.add.noftz.v2.f16x2 [%0], {%1, %2};"
                 :: "l"(a), "r"(ulo), "r"(uhi)
                 : "memory");
}

__global__ void __launch_bounds__(256) k_scatter(
        const float4* __restrict__ r3, const float4* __restrict__ c3,
        const float4* __restrict__ r4, const float4* __restrict__ c4) {
    int i = blockIdx.x * blockDim.x + threadIdx.x;   // [0, PTS/4)
    if (i >= PTS / 4) return;
    int s = i >> 19;                                 // scale (MAPSZ/4 = 2^19)
    int b = (i >> 16) & 7;                           // batch within scale

    float4 rA = r3[i], cA = c3[i];
    float4 rB = r4[i], cB = c4[i];
    scat1(s, b, rA.x, cA.x); scat1(s, b, rA.y, cA.y);
    scat1(s, b, rA.z, cA.z); scat1(s, b, rA.w, cA.w);
    scat1(s, b, rB.x, cB.x); scat1(s, b, rB.y, cB.y);
    scat1(s, b, rB.z, cB.z); scat1(s, b, rB.w, cB.w);
}

// ---------------------------------------------------------------------------
// K2: fused combine + max + masked log-stats + INTERIOR restore-to-zero.
// CTA = 8x32 threads over (bx block-of-8, byp block-of-32). Cross-CTA reads
// only touch ty==0 rows / tx==0 cols of neighbor blocks — never zeroed here
// (k_sweep gets them). Target mask from g_mask (2 x 32-bit loads/thread).
// BCE algebra: sum_{mask} min(lm - log(dm), 100)
//   = (npos - nzero)*lm - sum_{mask,dm>0} log(dm) + 100*nzero
// ---------------------------------------------------------------------------
__device__ __forceinline__ float lohalf(unsigned u) { return __half2float(__ushort_as_half((unsigned short)(u & 0xFFFF))); }
__device__ __forceinline__ float hihalf(unsigned u) { return __half2float(__ushort_as_half((unsigned short)(u >> 16))); }

__device__ __forceinline__ void stat_cell(float d, unsigned bit, float& sl,
                                          unsigned& nz) {
    if (bit) {
        if (d == 0.f) nz++;
        else sl += __logf(d);
    }
}

__global__ void __launch_bounds__(256) k_stats() {
    // blockIdx.x in [0, 7168): s | b | bxblk(32) | bypblk(4)
    const int s      = blockIdx.x >> 10;
    const int rem    = blockIdx.x & 1023;
    const int b      = rem >> 7;
    const int bxblk  = (rem >> 2) & 31;
    const int bypblk = rem & 3;
    const int tx = threadIdx.x & 31;     // byp within block
    const int ty = threadIdx.x >> 5;     // bx within block
    const int bx  = bxblk * 8 + ty;
    const int byp = bypblk * 32 + tx;
    const int by  = byp * 2;
    const int t00 = b * MAPH + bx * TTY + by;    // 16B aligned (TTY, by even)

    uint2* __restrict__ w00 = g_rep[s][0];
    uint2* __restrict__ w01 = g_rep[s][1];
    uint2* __restrict__ w10 = g_rep[s][2];
    uint2* __restrict__ w11 = g_rep[s][3];

    float mx, sl = 0.f;
    unsigned nz = 0, np = 0;
    {
        uint4 A  = *(const uint4*)(w00 + t00);
        uint4 B0 = *(const uint4*)(w01 + t00);
        uint2 B2 = w01[t00 + 2];
        uint4 C0 = *(const uint4*)(w10 + t00);
        uint4 C1 = *(const uint4*)(w10 + t00 + TTY);
        uint4 D0 = *(const uint4*)(w11 + t00);
        uint2 D2 = w11[t00 + 2];
        uint4 D1 = *(const uint4*)(w11 + t00 + TTY);
        uint2 D3 = w11[t00 + TTY + 2];

        // home tile 0: logical block (bx, by); home tile 1: (bx, by+1)
        float a00 = lohalf(A.x) + hihalf(B0.x) + lohalf(C0.y) + hihalf(D0.y);
        float a01 = hihalf(A.x) + lohalf(B0.z) + hihalf(C0.y) + lohalf(D0.w);
        float a10 = lohalf(A.y) + hihalf(B0.y) + lohalf(C1.x) + hihalf(D1.x);
        float a11 = hihalf(A.y) + lohalf(B0.w) + hihalf(C1.x) + lohalf(D1.z);
        float e00 = lohalf(A.z) + hihalf(B0.z) + lohalf(C0.w) + hihalf(D0.w);
        float e01 = hihalf(A.z) + lohalf(B2.x) + hihalf(C0.w) + lohalf(D2.y);
        float e10 = lohalf(A.w) + hihalf(B0.w) + lohalf(C1.z) + hihalf(D1.z);
        float e11 = hihalf(A.w) + lohalf(B2.y) + hihalf(C1.z) + lohalf(D3.x);

        mx = fmaxf(fmaxf(fmaxf(a00, a01), fmaxf(a10, a11)),
                   fmaxf(fmaxf(e00, e01), fmaxf(e10, e11)));

        // mask: rows 2bx, 2bx+1; logical col base C = 2*by = 4*byp
        const unsigned* mrow = g_mask + ((b * ADIM + 2 * bx) * 16) + (byp >> 3);
        unsigned mw0 = mrow[0];        // row 2bx
        unsigned mw1 = mrow[16];       // row 2bx+1
        int sh = 4 * (byp & 7);
        unsigned m0 = (mw0 >> sh) & 0xFu;   // cols C..C+3 -> a00,a01,e00,e01
        unsigned m1 = (mw1 >> sh) & 0xFu;   // -> a10,a11,e10,e11
        np = __popc(m0) + __popc(m1);

        stat_cell(a00, m0 & 1u, sl, nz);
        stat_cell(a01, m0 & 2u, sl, nz);
        stat_cell(e00, m0 & 4u, sl, nz);
        stat_cell(e01, m0 & 8u, sl, nz);
        stat_cell(a10, m1 & 1u, sl, nz);
        stat_cell(a11, m1 & 2u, sl, nz);
        stat_cell(e10, m1 & 4u, sl, nz);
        stat_cell(e11, m1 & 8u, sl, nz);
    }
    #pragma unroll
    for (int o = 16; o; o >>= 1) {
        mx = fmaxf(mx, __shfl_xor_sync(0xFFFFFFFFu, mx, o));
        sl += __shfl_xor_sync(0xFFFFFFFFu, sl, o);
        nz += __shfl_xor_sync(0xFFFFFFFFu, nz, o);
        np += __shfl_xor_sync(0xFFFFFFFFu, np, o);
    }
    __shared__ float    smx[8], ssl[8];
    __shared__ unsigned snz[8], snp[8];
    int w = threadIdx.x >> 5;
    if ((threadIdx.x & 31) == 0) { smx[w] = mx; ssl[w] = sl; snz[w] = nz; snp[w] = np; }
    __syncthreads();   // orders: ALL CTA loads above complete before zeroing

    // Interior restore: zero own home uint4 in all 4 replicas. ty==0 / tx==0
    // tiles are read by neighbor CTAs -> left for k_sweep.
    if (ty != 0 && tx != 0) {
        const uint4 z = make_uint4(0u, 0u, 0u, 0u);
        *(uint4*)(w00 + t00) = z;
        *(uint4*)(w01 + t00) = z;
        *(uint4*)(w10 + t00) = z;
        *(uint4*)(w11 + t00) = z;
    }

    if (threadIdx.x == 0) {
        float bmx = smx[0], bsl = ssl[0];
        unsigned bnz = snz[0], bnp = snp[0];
        #pragma unroll
        for (int k = 1; k < 8; k++) {
            bmx = fmaxf(bmx, smx[k]); bsl += ssl[k]; bnz += snz[k]; bnp += snp[k];
        }
        atomicMax(&g_max[s], __float_as_uint(bmx));
        atomicAdd(&g_sumlog[s], bsl);
        if (bnz) atomicAdd(&g_nzero[s], bnz);
        if (s == 0) atomicAdd(&g_npos, bnp);
    }
}

// ---------------------------------------------------------------------------
// K3: sweep — zero the boundary tiles k_stats skipped (tile rows r % 8 == 0
// plus row 256; col pairs {0,1}+{64k,64k+1}+{256,257}), for all 224
// (scale,replica,map) planes. ~20 MB. Block 0 also computes the final loss
// (stats already completed in stream order) and resets accumulators.
// ---------------------------------------------------------------------------
#define RM   (NSC * 4 * NB)            // 224 planes
#define ROWI (33 * 129)                // row part: 33 rows x 129 uint4
#define COLI (5 * 257)                 // col part: 5 uint4-cols x 257 rows
#define SWI  (ROWI + COLI)             // 5542 uint4 per plane

__global__ void __launch_bounds__(256) k_sweep(float* __restrict__ out) {
    int gid = blockIdx.x * blockDim.x + threadIdx.x;
    if (gid < RM * SWI) {
        int rm   = gid / SWI;
        int rest = gid - rm * SWI;
        int r, c;
        if (rest < ROWI) {           // full rows 0,8,...,256
            int rr = rest / 129;
            r = rr * 8;
            c = (rest - rr * 129) * 2;
        } else {                     // cols {0,64,128,192,256} (uint4 pairs)
            int t = rest - ROWI;
            int ci = t / 257;
            c = ci * 64;
            r = t - ci * 257;
        }
        uint2* base = &g_rep[0][0][0] + (size_t)rm * MAPH;
        *(uint4*)(base + r * TTY + c) = make_uint4(0u, 0u, 0u, 0u);
    }
    if (blockIdx.x == 0 && threadIdx.x == 0) {
        float np = (float)g_npos;
        float tot = 0.f;
        #pragma unroll
        for (int i = 0; i < NSC; i++) {
            float lm = logf(__uint_as_float(g_max[i]));
            float nzf = (float)g_nzero[i];
            tot += ((np - nzf) * lm - g_sumlog[i] + 100.f * nzf) / np;
            g_sumlog[i] = 0.f; g_max[i] = 0u; g_nzero[i] = 0u;
        }
        g_npos = 0u;
        out[0] = tot;
    }
}

// ---------------------------------------------------------------------------
// Launch: mask -> scatter -> stats(+interior restore) -> sweep(+final)
// ---------------------------------------------------------------------------
extern "C" void kernel_launch(void* const* d_in, const int* in_sizes, int n_in,
                              void* d_out, int out_size) {
    const float4* r3 = (const float4*)d_in[0];
    const float4* c3 = (const float4*)d_in[1];
    const float4* r4 = (const float4*)d_in[2];
    const float4* c4 = (const float4*)d_in[3];
    const float4* target = (const float4*)d_in[4];
    float* out = (float*)d_out;

    k_mask<<<MAPSZ / 32 / 256, 256>>>(target);             // 256 CTAs
    k_scatter<<<PTS / 4 / 256, 256>>>(r3, c3, r4, c4);     // 14336 CTAs
    k_stats<<<NSC * 1024, 256>>>();                        // 7168 CTAs
    k_sweep<<<(RM * SWI + 255) / 256, 256>>>(out);         // 4850 CTAs
}

// round 15
// speedup vs baseline: 1.0265x; 1.0188x over previous
#include <cuda_runtime.h>
#include <cuda_fp16.h>
#include <math.h>

#define NSC 7
#define NB 8
#define ADIM 512
#define MAPSZ (NB * ADIM * ADIM)       // 2,097,152 cells per scale
#define PTS (NSC * MAPSZ)              // 14,680,064 points per coord set
#define TTY 258                        // tile-row stride (even for uint4)
#define TTX 257                        // tile rows
#define MAPH (TTX * TTY)               // 66306 tiles (8B each) per (map, replica)

// Scratch: 4 shift-replicas per scale; each 2x2 logical tile = 4 x f16 = uint2.
// ~119 MB. INVARIANT: all-zero at entry to every kernel_launch call
// (__device__ globals zero-init at load; k_stats/k_sweep re-zero after use).
__device__ __align__(16) uint2 g_rep[NSC][4][NB * MAPH];
__device__ unsigned int g_mask[MAPSZ / 32];   // 1 bit/cell; fully rewritten each call
__device__ float        g_sumlog[NSC];
__device__ unsigned int g_max[NSC];     // float bits (values >= 0)
__device__ unsigned int g_nzero[NSC];
__device__ unsigned int g_npos;

// ---------------------------------------------------------------------------
// K1: bilinear scatter, ALL scales — ONE red.global.add.noftz.v2.f16x2 per
// point. Replica (sx,sy) stores logical (x,y) at (x+sx, y+sy); sx=ixf&1,
// sy=iyf&1 puts the 2x2 footprint in exactly one aligned tile.
// Tile halves [0..3] = (dx,dy) = (0,0),(0,1),(1,0),(1,1).
// (At the L1tex wavefront floor ~1 lane/cyc/SM for random addresses.)
// FUSED: first 65536 threads also build the target bitmask (scatter has 84%
// issue slack; removes a separate kernel + gap).
// ---------------------------------------------------------------------------
__device__ __forceinline__ void scat1(int s, int b, float r, float c) {
    float xf = fminf(fmaxf(floorf(r), 0.f), 511.f);
    float yf = fminf(fmaxf(floorf(c), 0.f), 511.f);
    float xw = r - xf;
    float yw = c - yf;
    int ix = (int)xf, iy = (int)yf;
    int sx = ix & 1, sy = iy & 1;
    uint2* a = &g_rep[s][sx * 2 + sy][b * MAPH + ((ix + sx) >> 1) * TTY + ((iy + sy) >> 1)];
    float wx0 = 1.f - xw, wy0 = 1.f - yw;
    __half2 lo = __floats2half2_rn(wx0 * wy0, wx0 * yw);   // (0,0),(0,1)
    __half2 hi = __floats2half2_rn(xw * wy0,  xw * yw);    // (1,0),(1,1)
    unsigned ulo = *reinterpret_cast<unsigned*>(&lo);
    unsigned uhi = *reinterpret_cast<unsigned*>(&hi);
    asm volatile("red.global.add.noftz.v2.f16x2 [%0], {%1, %2};"
                 :: "l"(a), "r"(ulo), "r"(uhi)
                 : "memory");
}

__global__ void __launch_bounds__(256) k_scatter(
        const float4* __restrict__ r3, const float4* __restrict__ c3,
        const float4* __restrict__ r4, const float4* __restrict__ c4,
        const float4* __restrict__ target) {
    int i = blockIdx.x * blockDim.x + threadIdx.x;   // [0, PTS/4)

    // Fused mask build: bit c of word (b*512+r)*16 + c/32 = (target==1).
    // 4-bit nibbles (4-aligned cols) never straddle a word.
    if (i < MAPSZ / 32) {
        const float4* tp = target + i * 8;           // 32 cells
        unsigned m = 0;
        #pragma unroll
        for (int j = 0; j < 8; j++) {
            float4 t = tp[j];
            m |= (t.x == 1.0f ? 1u : 0u) << (4 * j);
            m |= (t.y == 1.0f ? 2u : 0u) << (4 * j);
            m |= (t.z == 1.0f ? 4u : 0u) << (4 * j);
            m |= (t.w == 1.0f ? 8u : 0u) << (4 * j);
        }
        g_mask[i] = m;
    }

    if (i >= PTS / 4) return;
    int s = i >> 19;                                 // scale (MAPSZ/4 = 2^19)
    int b = (i >> 16) & 7;                           // batch within scale

    float4 rA = r3[i], cA = c3[i];
    float4 rB = r4[i], cB = c4[i];
    scat1(s, b, rA.x, cA.x); scat1(s, b, rA.y, cA.y);
    scat1(s, b, rA.z, cA.z); scat1(s, b, rA.w, cA.w);
    scat1(s, b, rB.x, cB.x); scat1(s, b, rB.y, cB.y);
    scat1(s, b, rB.z, cB.z); scat1(s, b, rB.w, cB.w);
}

// ---------------------------------------------------------------------------
// K2: fused combine + max + masked log-stats + INTERIOR restore-to-zero.
// CTA = 8x32 threads over (bx block-of-8, byp block-of-32). Cross-CTA reads
// only touch ty==0 rows / tx==0 cols of neighbor blocks — never zeroed here
// (k_sweep gets them). Target mask from g_mask (2 x 32-bit loads/thread).
// PDL: launched with ProgrammaticStreamSerialization; grid-dependency sync
// before touching scatter's outputs.
// BCE algebra: sum_{mask} min(lm - log(dm), 100)
//   = (npos - nzero)*lm - sum_{mask,dm>0} log(dm) + 100*nzero
// ---------------------------------------------------------------------------
__device__ __forceinline__ float lohalf(unsigned u) { return __half2float(__ushort_as_half((unsigned short)(u & 0xFFFF))); }
__device__ __forceinline__ float hihalf(unsigned u) { return __half2float(__ushort_as_half((unsigned short)(u >> 16))); }

__device__ __forceinline__ void stat_cell(float d, unsigned bit, float& sl,
                                          unsigned& nz) {
    if (bit) {
        if (d == 0.f) nz++;
        else sl += __logf(d);
    }
}

__global__ void __launch_bounds__(256) k_stats() {
    // blockIdx.x in [0, 7168): s | b | bxblk(32) | bypblk(4)
    const int s      = blockIdx.x >> 10;
    const int rem    = blockIdx.x & 1023;
    const int b      = rem >> 7;
    const int bxblk  = (rem >> 2) & 31;
    const int bypblk = rem & 3;
    const int tx = threadIdx.x & 31;     // byp within block
    const int ty = threadIdx.x >> 5;     // bx within block
    const int bx  = bxblk * 8 + ty;
    const int byp = bypblk * 32 + tx;
    const int by  = byp * 2;
    const int t00 = b * MAPH + bx * TTY + by;    // 16B aligned (TTY, by even)

    cudaGridDependencySynchronize();     // wait for scatter (PDL)

    uint2* __restrict__ w00 = g_rep[s][0];
    uint2* __restrict__ w01 = g_rep[s][1];
    uint2* __restrict__ w10 = g_rep[s][2];
    uint2* __restrict__ w11 = g_rep[s][3];

    float mx, sl = 0.f;
    unsigned nz = 0, np = 0;
    {
        uint4 A  = *(const uint4*)(w00 + t00);
        uint4 B0 = *(const uint4*)(w01 + t00);
        uint2 B2 = w01[t00 + 2];
        uint4 C0 = *(const uint4*)(w10 + t00);
        uint4 C1 = *(const uint4*)(w10 + t00 + TTY);
        uint4 D0 = *(const uint4*)(w11 + t00);
        uint2 D2 = w11[t00 + 2];
        uint4 D1 = *(const uint4*)(w11 + t00 + TTY);
        uint2 D3 = w11[t00 + TTY + 2];

        // home tile 0: logical block (bx, by); home tile 1: (bx, by+1)
        float a00 = lohalf(A.x) + hihalf(B0.x) + lohalf(C0.y) + hihalf(D0.y);
        float a01 = hihalf(A.x) + lohalf(B0.z) + hihalf(C0.y) + lohalf(D0.w);
        float a10 = lohalf(A.y) + hihalf(B0.y) + lohalf(C1.x) + hihalf(D1.x);
        float a11 = hihalf(A.y) + lohalf(B0.w) + hihalf(C1.x) + lohalf(D1.z);
        float e00 = lohalf(A.z) + hihalf(B0.z) + lohalf(C0.w) + hihalf(D0.w);
        float e01 = hihalf(A.z) + lohalf(B2.x) + hihalf(C0.w) + lohalf(D2.y);
        float e10 = lohalf(A.w) + hihalf(B0.w) + lohalf(C1.z) + hihalf(D1.z);
        float e11 = hihalf(A.w) + lohalf(B2.y) + hihalf(C1.z) + lohalf(D3.x);

        mx = fmaxf(fmaxf(fmaxf(a00, a01), fmaxf(a10, a11)),
                   fmaxf(fmaxf(e00, e01), fmaxf(e10, e11)));

        // mask: rows 2bx, 2bx+1; logical col base C = 2*by = 4*byp
        const unsigned* mrow = g_mask + ((b * ADIM + 2 * bx) * 16) + (byp >> 3);
        unsigned mw0 = mrow[0];        // row 2bx
        unsigned mw1 = mrow[16];       // row 2bx+1
        int sh = 4 * (byp & 7);
        unsigned m0 = (mw0 >> sh) & 0xFu;   // cols C..C+3 -> a00,a01,e00,e01
        unsigned m1 = (mw1 >> sh) & 0xFu;   // -> a10,a11,e10,e11
        np = __popc(m0) + __popc(m1);

        stat_cell(a00, m0 & 1u, sl, nz);
        stat_cell(a01, m0 & 2u, sl, nz);
        stat_cell(e00, m0 & 4u, sl, nz);
        stat_cell(e01, m0 & 8u, sl, nz);
        stat_cell(a10, m1 & 1u, sl, nz);
        stat_cell(a11, m1 & 2u, sl, nz);
        stat_cell(e10, m1 & 4u, sl, nz);
        stat_cell(e11, m1 & 8u, sl, nz);
    }
    #pragma unroll
    for (int o = 16; o; o >>= 1) {
        mx = fmaxf(mx, __shfl_xor_sync(0xFFFFFFFFu, mx, o));
        sl += __shfl_xor_sync(0xFFFFFFFFu, sl, o);
        nz += __shfl_xor_sync(0xFFFFFFFFu, nz, o);
        np += __shfl_xor_sync(0xFFFFFFFFu, np, o);
    }
    __shared__ float    smx[8], ssl[8];
    __shared__ unsigned snz[8], snp[8];
    int w = threadIdx.x >> 5;
    if ((threadIdx.x & 31) == 0) { smx[w] = mx; ssl[w] = sl; snz[w] = nz; snp[w] = np; }
    __syncthreads();   // orders: ALL CTA loads above complete before zeroing

    // Interior restore: zero own home uint4 in all 4 replicas. ty==0 / tx==0
    // tiles are read by neighbor CTAs -> left for k_sweep.
    if (ty != 0 && tx != 0) {
        const uint4 z = make_uint4(0u, 0u, 0u, 0u);
        *(uint4*)(w00 + t00) = z;
        *(uint4*)(w01 + t00) = z;
        *(uint4*)(w10 + t00) = z;
        *(uint4*)(w11 + t00) = z;
    }

    if (threadIdx.x == 0) {
        float bmx = smx[0], bsl = ssl[0];
        unsigned bnz = snz[0], bnp = snp[0];
        #pragma unroll
        for (int k = 1; k < 8; k++) {
            bmx = fmaxf(bmx, smx[k]); bsl += ssl[k]; bnz += snz[k]; bnp += snp[k];
        }
        atomicMax(&g_max[s], __float_as_uint(bmx));
        atomicAdd(&g_sumlog[s], bsl);
        if (bnz) atomicAdd(&g_nzero[s], bnz);
        if (s == 0) atomicAdd(&g_npos, bnp);
    }
}

// ---------------------------------------------------------------------------
// K3: sweep — zero the boundary tiles k_stats skipped (tile rows r % 8 == 0
// plus row 256; col pairs {0,1}+{64k,64k+1}+{256,257}), for all 224
// (scale,replica,map) planes. ~20 MB. Block 0 also computes the final loss
// and resets accumulators. PDL-launched after stats.
// ---------------------------------------------------------------------------
#define RM   (NSC * 4 * NB)            // 224 planes
#define ROWI (33 * 129)                // row part: 33 rows x 129 uint4
#define COLI (5 * 257)                 // col part: 5 uint4-cols x 257 rows
#define SWI  (ROWI + COLI)             // 5542 uint4 per plane

__global__ void __launch_bounds__(256) k_sweep(float* __restrict__ out) {
    int gid = blockIdx.x * blockDim.x + threadIdx.x;
    int rm = 0, rest = 0, r = 0, c = 0;
    if (gid < RM * SWI) {              // index math before the dependency wait
        rm   = gid / SWI;
        rest = gid - rm * SWI;
        if (rest < ROWI) {             // full rows 0,8,...,256
            int rr = rest / 129;
            r = rr * 8;
            c = (rest - rr * 129) * 2;
        } else {                       // cols {0,64,128,192,256} (uint4 pairs)
            int t = rest - ROWI;
            int ci = t / 257;
            c = ci * 64;
            r = t - ci * 257;
        }
    }
    cudaGridDependencySynchronize();   // wait for stats (PDL)
    if (gid < RM * SWI) {
        uint2* base = &g_rep[0][0][0] + (size_t)rm * MAPH;
        *(uint4*)(base + r * TTY + c) = make_uint4(0u, 0u, 0u, 0u);
    }
    if (blockIdx.x == 0 && threadIdx.x == 0) {
        float np = (float)g_npos;
        float tot = 0.f;
        #pragma unroll
        for (int i = 0; i < NSC; i++) {
            float lm = logf(__uint_as_float(g_max[i]));
            float nzf = (float)g_nzero[i];
            tot += ((np - nzf) * lm - g_sumlog[i] + 100.f * nzf) / np;
            g_sumlog[i] = 0.f; g_max[i] = 0u; g_nzero[i] = 0u;
        }
        g_npos = 0u;
        out[0] = tot;
    }
}

// ---------------------------------------------------------------------------
// Launch: scatter(+mask) -> [PDL] stats(+interior restore) -> [PDL] sweep(+final)
// ---------------------------------------------------------------------------
extern "C" void kernel_launch(void* const* d_in, const int* in_sizes, int n_in,
                              void* d_out, int out_size) {
    const float4* r3 = (const float4*)d_in[0];
    const float4* c3 = (const float4*)d_in[1];
    const float4* r4 = (const float4*)d_in[2];
    const float4* c4 = (const float4*)d_in[3];
    const float4* target = (const float4*)d_in[4];
    float* out = (float*)d_out;

    k_scatter<<<PTS / 4 / 256, 256>>>(r3, c3, r4, c4, target);  // 14336 CTAs

    cudaLaunchAttribute attr[1];
    attr[0].id = cudaLaunchAttributeProgrammaticStreamSerialization;
    attr[0].val.programmaticStreamSerializationAllowed = 1;

    cudaLaunchConfig_t cfgS = {};
    cfgS.gridDim = dim3(NSC * 1024);     // 7168 CTAs
    cfgS.blockDim = dim3(256);
    cfgS.attrs = attr;
    cfgS.numAttrs = 1;
    cudaLaunchKernelEx(&cfgS, k_stats);

    cudaLaunchConfig_t cfgW = {};
    cfgW.gridDim = dim3((RM * SWI + 255) / 256);   // 4850 CTAs
    cfgW.blockDim = dim3(256);
    cfgW.attrs = attr;
    cfgW.numAttrs = 1;
    cudaLaunchKernelEx(&cfgW, k_sweep, out);
}